// round 11
// baseline (speedup 1.0000x reference)
#include <cuda_runtime.h>
#include <cstdint>

// ---------------------------------------------------------------------------
// Shapes
// ---------------------------------------------------------------------------
#define BT   12
#define CF   1024
#define CQ   128
#define NTOK 2401
#define NP   2432
#define HF   49

// ---------------------------------------------------------------------------
// Scratch (prepared-operand buffers)
// ---------------------------------------------------------------------------
__device__ float g_X  [(size_t)BT * CF * NP];   // residual [bt][c][n]
__device__ float g_XTh[(size_t)BT * NP * CF];   // XT hi, k-permuted
__device__ float g_XTl[(size_t)BT * NP * CF];   // XT lo, k-permuted
__device__ float g_Wqh[(size_t)CQ * CF];
__device__ float g_Wql[(size_t)CQ * CF];
__device__ float g_Wkh[(size_t)CQ * CF];
__device__ float g_Wkl[(size_t)CQ * CF];
__device__ float g_Wvh[(size_t)CF * CF];
__device__ float g_QTh[(size_t)BT * NP * CQ];
__device__ float g_QTl[(size_t)BT * NP * CQ];
__device__ float g_KTh[(size_t)BT * NP * CQ];
__device__ float g_KTl[(size_t)BT * NP * CQ];
__device__ float g_Vh [(size_t)BT * CF * NP];   // V hi, n-permuted
__device__ float g_ATT[(size_t)BT * NP * NP];   // scores raw, then probs (permuted)

__device__ __forceinline__ uint32_t f2tf(float f) {
    uint32_t u; asm("cvt.rna.tf32.f32 %0, %1;" : "=r"(u) : "f"(f)); return u;
}
__device__ __forceinline__ float tf32f(float f) { return __uint_as_float(f2tf(f)); }
__device__ __forceinline__ uint32_t smem_u32(const void* p) {
    uint32_t a;
    asm("{ .reg .u64 t; cvta.to.shared.u64 t, %1; cvt.u32.u64 %0, t; }" : "=r"(a) : "l"(p));
    return a;
}
__device__ __forceinline__ int permk(int k) { return (k < 4) ? (2 * k) : (2 * (k - 4) + 1); }
__device__ __forceinline__ int invp(int p)  { return (p & 1) ? ((p >> 1) + 4) : (p >> 1); }

__device__ __forceinline__ void mma_tf32(float c[4], const uint32_t a[4], const uint32_t b[2]) {
    asm volatile(
        "mma.sync.aligned.m16n8k8.row.col.f32.tf32.tf32.f32 "
        "{%0,%1,%2,%3}, {%4,%5,%6,%7}, {%8,%9}, {%0,%1,%2,%3};"
        : "+f"(c[0]), "+f"(c[1]), "+f"(c[2]), "+f"(c[3])
        : "r"(a[0]), "r"(a[1]), "r"(a[2]), "r"(a[3]), "r"(b[0]), "r"(b[1]));
}

#define CP_ASYNC16(dst_u32, src_ptr) \
    asm volatile("cp.async.cg.shared.global [%0], [%1], 16;" :: "r"(dst_u32), "l"(src_ptr) : "memory")
#define CP_COMMIT() asm volatile("cp.async.commit_group;" ::: "memory")
#define CP_WAIT0()  asm volatile("cp.async.wait_group 0;" ::: "memory")
#define CP_WAIT1()  asm volatile("cp.async.wait_group 1;" ::: "memory")

// ---------------------------------------------------------------------------
// 1a) residual X[bt][c][n]
// ---------------------------------------------------------------------------
__global__ void build_x_kernel(const float* __restrict__ img,
                               const float* __restrict__ tac) {
    int n = blockIdx.x * 256 + threadIdx.x;
    int c = blockIdx.y, bt = blockIdx.z;
    if (n >= NP) return;
    float v = 0.0f;
    if (n < NTOK) {
        int i = n / HF, j = n % HF;
        v = (c < 512)
            ? tac[(((size_t)bt * 512 + c) * 7 + (i / 7)) * 7 + (j / 7)]
            : img[(((size_t)bt * 512 + (c - 512)) * 7 + (i % 7)) * 7 + (j % 7)];
    }
    g_X[((size_t)bt * CF + c) * NP + n] = v;
}

// ---------------------------------------------------------------------------
// 1b) XT hi/lo, k-permuted over c
// ---------------------------------------------------------------------------
__global__ void build_xt_kernel(const float* __restrict__ img,
                                const float* __restrict__ tac) {
    int c = blockIdx.x * 256 + threadIdx.x;
    int n = blockIdx.y, bt = blockIdx.z;
    if (c >= CF) return;
    float v = 0.0f;
    if (n < NTOK) {
        int i = n / HF, j = n % HF;
        v = (c < 512)
            ? tac[(((size_t)bt * 512 + c) * 7 + (i / 7)) * 7 + (j / 7)]
            : img[(((size_t)bt * 512 + (c - 512)) * 7 + (i % 7)) * 7 + (j % 7)];
    }
    float h = tf32f(v);
    int cp = (c & ~7) | permk(c & 7);
    size_t base = ((size_t)bt * NP + n) * CF + cp;
    g_XTh[base] = h;
    g_XTl[base] = tf32f(v - h);
}

// ---------------------------------------------------------------------------
// 1c) weight prep
// ---------------------------------------------------------------------------
__global__ void prep_split_kernel(const float* __restrict__ src,
                                  float* __restrict__ dh, float* __restrict__ dl, int n) {
    int i = blockIdx.x * 256 + threadIdx.x;
    if (i >= n) return;
    float v = src[i];
    float h = tf32f(v);
    int tgt = (i & ~7) | permk(i & 7);
    dh[tgt] = h;
    dl[tgt] = tf32f(v - h);
}
__global__ void prep_round_kernel(const float* __restrict__ src,
                                  float* __restrict__ dh, int n) {
    int i = blockIdx.x * 256 + threadIdx.x;
    if (i >= n) return;
    int tgt = (i & ~7) | permk(i & 7);
    dh[tgt] = tf32f(src[i]);
}

// ---------------------------------------------------------------------------
// 2) softmax: read raw S rows, write rounded probs at permuted positions
// ---------------------------------------------------------------------------
__global__ __launch_bounds__(256)
void softmax_kernel() {
    __shared__ float row[NTOK];
    __shared__ float red[256];
    const int n = blockIdx.x, bt = blockIdx.y;
    float* base = g_ATT + ((size_t)bt * NP + n) * NP;
    const int t = threadIdx.x;

    float mx = -1e30f;
    for (int m = t; m < NTOK; m += 256) { float v = base[m]; row[m] = v; mx = fmaxf(mx, v); }
    red[t] = mx; __syncthreads();
    for (int s = 128; s > 0; s >>= 1) { if (t < s) red[t] = fmaxf(red[t], red[t + s]); __syncthreads(); }
    mx = red[0]; __syncthreads();

    float sum = 0.0f;
    for (int m = t; m < NTOK; m += 256) { float e = __expf(row[m] - mx); row[m] = e; sum += e; }
    red[t] = sum; __syncthreads();
    for (int s = 128; s > 0; s >>= 1) { if (t < s) red[t] += red[t + s]; __syncthreads(); }
    float inv = 1.0f / red[0];
    __syncthreads();

    for (int m = t; m < NTOK; m += 256) {
        int tgt = (m & ~7) | permk(m & 7);
        base[tgt] = tf32f(row[m] * inv);
    }
    for (int m = NTOK + t; m < NP; m += 256) {
        int tgt = (m & ~7) | permk(m & 7);
        base[tgt] = 0.0f;
    }
}

// ---------------------------------------------------------------------------
// Tiling constants
// ---------------------------------------------------------------------------
#define S1 40                       // SPLIT1 smem row stride (words), chunk 32
#define STG1 (256 * S1)             // words per stage (A128 + B128)
#define SMEM_S1 (2 * STG1 * 4)      // 81920 B

#define S3 24                       // SPLIT3 smem row stride (words), chunk 16
#define STG3 (4 * 128 * S3)         // words per stage (Ah, Al, Bh, Bl)
#define SMEM_S3 (2 * STG3 * 4)      // 98304 B

#define SS 132                      // epilogue staging stride

// ---------------------------------------------------------------------------
// 3) SPLIT=1 prepared-operand GEMM: C[M,N] = A[M,K] @ B[N,K]^T,
//    operands pre-rounded + k-permuted in global. 256 thr (8 warps 2Mx4N,
//    warp tile 64x32), chunk 32, 2-stage cp.async, 2 CTAs/SM. No cvt.
//    EPI 0: V-writeback — stage, add bias[row], round, permute cols, C=V_hi
//    EPI 1: out = gamma*acc + X[row][col], col<NTOK, scalar masked stores
// ---------------------------------------------------------------------------
template <int EPI>
__global__ __launch_bounds__(256, 2)
void gemm_s1_kernel(const float* __restrict__ A, int lda, size_t strideA,
                    const float* __restrict__ B, int ldb, size_t strideB,
                    int K,
                    const float* __restrict__ bias,
                    const float* __restrict__ gamma,
                    const float* __restrict__ Xres,
                    float* __restrict__ C, int ldc, size_t strideC) {
    extern __shared__ uint32_t sm[];
    const uint32_t smem_base = smem_u32(sm);

    const int bt = blockIdx.z;
    const int m0 = blockIdx.x * 128;
    const int n0 = blockIdx.y * 128;
    const float* Ab = A + (size_t)bt * strideA + (size_t)m0 * lda;
    const float* Bb = B + (size_t)bt * strideB + (size_t)n0 * ldb;

    const int t = threadIdx.x;
    const int wid = t >> 5, lane = t & 31;
    const int wm = wid & 1, wn = wid >> 1;
    const int l4 = lane >> 2, lm = lane & 3;

    // producer: t<128 -> A row t; t>=128 -> B row t-128; 8 rotated granules
    const bool isA = (t < 128);
    const int prow = t & 127;
    const float* gRow = isA ? (Ab + (size_t)prow * lda) : (Bb + (size_t)prow * ldb);
    const uint32_t sDst0 = smem_base + (uint32_t)(((isA ? 0 : 128 * S1) + prow * S1) * 4);
    const int qrot = lane & 7;

    float acc[4][4][4];
    #pragma unroll
    for (int mi = 0; mi < 4; mi++)
        #pragma unroll
        for (int ni = 0; ni < 4; ni++)
            #pragma unroll
            for (int r = 0; r < 4; r++) acc[mi][ni][r] = 0.0f;

    const int NCH = K / 32;

    #define S1_ISSUE(stg, koff) do {                                           \
        const uint32_t _d = sDst0 + (uint32_t)(stg) * (STG1 * 4);              \
        _Pragma("unroll")                                                      \
        for (int i = 0; i < 8; i++) {                                          \
            const int q = (i + qrot) & 7;                                      \
            CP_ASYNC16(_d + q * 16, gRow + (koff) + q * 4);                    \
        }                                                                      \
        CP_COMMIT();                                                           \
    } while (0)

    S1_ISSUE(0, 0);

    for (int ch = 0; ch < NCH; ch++) {
        const int buf = ch & 1;
        if (ch + 1 < NCH) {
            S1_ISSUE(buf ^ 1, (ch + 1) * 32);
            CP_WAIT1();
        } else {
            CP_WAIT0();
        }
        __syncthreads();

        const uint32_t* as = sm + buf * STG1;
        const uint32_t* bs = as + 128 * S1;
        #pragma unroll
        for (int g = 0; g < 4; g++) {
            const int kk = g * 8 + 2 * lm;
            uint32_t b[4][2];
            #pragma unroll
            for (int ni = 0; ni < 4; ni++) {
                uint2 bb = *reinterpret_cast<const uint2*>(&bs[(wn * 32 + ni * 8 + l4) * S1 + kk]);
                b[ni][0] = bb.x; b[ni][1] = bb.y;
            }
            #pragma unroll
            for (int mi = 0; mi < 4; mi++) {
                const int ro = (wm * 64 + mi * 16 + l4) * S1 + kk;
                uint2 A0 = *reinterpret_cast<const uint2*>(&as[ro]);
                uint2 A8 = *reinterpret_cast<const uint2*>(&as[ro + 8 * S1]);
                uint32_t a[4] = { A0.x, A8.x, A0.y, A8.y };
                #pragma unroll
                for (int ni = 0; ni < 4; ni++) mma_tf32(acc[mi][ni], a, b[ni]);
            }
        }
        __syncthreads();
    }
    #undef S1_ISSUE

    if (EPI == 0) {
        // stage, then rounded + col-permuted writeback (C = V_hi)
        float* stg = reinterpret_cast<float*>(sm);
        #pragma unroll
        for (int mi = 0; mi < 4; mi++) {
            const int r = wm * 64 + mi * 16 + l4;
            #pragma unroll
            for (int ni = 0; ni < 4; ni++) {
                const int c = wn * 32 + ni * 8 + 2 * lm;
                stg[r * SS + c]           = acc[mi][ni][0];
                stg[r * SS + c + 1]       = acc[mi][ni][1];
                stg[(r + 8) * SS + c]     = acc[mi][ni][2];
                stg[(r + 8) * SS + c + 1] = acc[mi][ni][3];
            }
        }
        __syncthreads();
        float* Cb = C + (size_t)bt * strideC;
        for (int e = t; e < 128 * 128; e += 256) {
            const int r = e >> 7, p = e & 127;
            const int j = (p & ~7) | invp(p & 7);
            float v = stg[r * SS + j] + bias[m0 + r];
            Cb[(size_t)(m0 + r) * ldc + n0 + p] = tf32f(v);
        }
    } else {
        const float g = __ldg(gamma);
        const float* Xb = Xres + (size_t)bt * CF * NP;
        float* Cb = C + (size_t)bt * strideC;
        #pragma unroll
        for (int mi = 0; mi < 4; mi++) {
            const int gr = m0 + wm * 64 + mi * 16 + l4;
            #pragma unroll
            for (int ni = 0; ni < 4; ni++) {
                const int gc = n0 + wn * 32 + ni * 8 + lm * 2;
                if (gc < NTOK)
                    Cb[(size_t)gr * ldc + gc] = g * acc[mi][ni][0] + Xb[(size_t)gr * NP + gc];
                if (gc + 1 < NTOK)
                    Cb[(size_t)gr * ldc + gc + 1] = g * acc[mi][ni][1] + Xb[(size_t)gr * NP + gc + 1];
                if (gc < NTOK)
                    Cb[(size_t)(gr + 8) * ldc + gc] = g * acc[mi][ni][2] + Xb[(size_t)(gr + 8) * NP + gc];
                if (gc + 1 < NTOK)
                    Cb[(size_t)(gr + 8) * ldc + gc + 1] = g * acc[mi][ni][3] + Xb[(size_t)(gr + 8) * NP + gc + 1];
            }
        }
    }
}

// ---------------------------------------------------------------------------
// 4) SPLIT=3 prepared-operand GEMM (3xTF32): operands pre-split hi/lo +
//    k-permuted in global. 256 thr (8 warps 2Mx4N), chunk 16, 2-stage
//    cp.async, 2 CTAs/SM. No cvt/sub in mainloop.
//    EPI 2: fused q/k projection (blockIdx.y selects), stage -> split+permute
//    EPI 3: raw scores, direct float2 stores
// ---------------------------------------------------------------------------
template <int EPI>
__global__ __launch_bounds__(256, 2)
void gemm_s3_kernel(const float* __restrict__ Ah, const float* __restrict__ Al,
                    int lda, size_t strideA,
                    const float* __restrict__ Bh, const float* __restrict__ Bl,
                    const float* __restrict__ B2h, const float* __restrict__ B2l,
                    int ldb, size_t strideB,
                    int K,
                    const float* __restrict__ bias, const float* __restrict__ bias2,
                    float* __restrict__ Ch, float* __restrict__ Cl,
                    float* __restrict__ C2h, float* __restrict__ C2l,
                    int ldc, size_t strideC) {
    extern __shared__ uint32_t sm[];
    const uint32_t smem_base = smem_u32(sm);

    const int bt = blockIdx.z;
    const int m0 = blockIdx.x * 128;
    int n0;
    const float *Bhs, *Bls, *biassel;
    float *Chs, *Cls;
    if (EPI == 2) {
        n0 = 0;
        const bool alt = (blockIdx.y != 0);
        Bhs = alt ? B2h : Bh;  Bls = alt ? B2l : Bl;
        biassel = alt ? bias2 : bias;
        Chs = alt ? C2h : Ch;  Cls = alt ? C2l : Cl;
    } else {
        n0 = blockIdx.y * 128;
        Bhs = Bh; Bls = Bl; biassel = bias; Chs = Ch; Cls = Cl;
    }

    const float* Ahb = Ah + (size_t)bt * strideA + (size_t)m0 * lda;
    const float* Alb = Al + (size_t)bt * strideA + (size_t)m0 * lda;
    const float* Bhb = Bhs + (size_t)bt * strideB + (size_t)n0 * ldb;
    const float* Blb = Bls + (size_t)bt * strideB + (size_t)n0 * ldb;

    const int t = threadIdx.x;
    const int wid = t >> 5, lane = t & 31;
    const int wm = wid & 1, wn = wid >> 1;
    const int l4 = lane >> 2, lm = lane & 3;

    // producer: tile = t>>6 (0:Ah 1:Al 2:Bh 3:Bl), 2 rows per thread, 4 granules each
    const int ptile = t >> 6, plocal = t & 63;
    const float* tsrc = (ptile == 0) ? Ahb : (ptile == 1) ? Alb : (ptile == 2) ? Bhb : Blb;
    const int pld = (ptile < 2) ? lda : ldb;
    const int pr0 = plocal * 2;
    const uint32_t pDst0 = smem_base + (uint32_t)((ptile * 128 * S3 + pr0 * S3) * 4);

    float acc[4][4][4];
    #pragma unroll
    for (int mi = 0; mi < 4; mi++)
        #pragma unroll
        for (int ni = 0; ni < 4; ni++)
            #pragma unroll
            for (int r = 0; r < 4; r++) acc[mi][ni][r] = 0.0f;

    const int NCH = K / 16;

    #define S3_ISSUE(stg, koff) do {                                           \
        const uint32_t _d = pDst0 + (uint32_t)(stg) * (STG3 * 4);              \
        _Pragma("unroll")                                                      \
        for (int i = 0; i < 8; i++) {                                          \
            const int rr = i >> 2, q = i & 3;                                  \
            CP_ASYNC16(_d + (rr * S3 * 4) + q * 16,                            \
                       tsrc + (size_t)(pr0 + rr) * pld + (koff) + q * 4);      \
        }                                                                      \
        CP_COMMIT();                                                           \
    } while (0)

    S3_ISSUE(0, 0);

    for (int ch = 0; ch < NCH; ch++) {
        const int buf = ch & 1;
        if (ch + 1 < NCH) {
            S3_ISSUE(buf ^ 1, (ch + 1) * 16);
            CP_WAIT1();
        } else {
            CP_WAIT0();
        }
        __syncthreads();

        const uint32_t* base_s = sm + buf * STG3;
        const uint32_t* ahs = base_s;
        const uint32_t* als = base_s + 128 * S3;
        const uint32_t* bhs = base_s + 2 * 128 * S3;
        const uint32_t* bls = base_s + 3 * 128 * S3;
        #pragma unroll
        for (int g = 0; g < 2; g++) {
            const int kk = g * 8 + 2 * lm;
            uint32_t bh[4][2], bl[4][2];
            #pragma unroll
            for (int ni = 0; ni < 4; ni++) {
                const int ro = (wn * 32 + ni * 8 + l4) * S3 + kk;
                uint2 hh = *reinterpret_cast<const uint2*>(&bhs[ro]);
                uint2 ll = *reinterpret_cast<const uint2*>(&bls[ro]);
                bh[ni][0] = hh.x; bh[ni][1] = hh.y;
                bl[ni][0] = ll.x; bl[ni][1] = ll.y;
            }
            #pragma unroll
            for (int mi = 0; mi < 4; mi++) {
                const int ro = (wm * 64 + mi * 16 + l4) * S3 + kk;
                uint2 H0 = *reinterpret_cast<const uint2*>(&ahs[ro]);
                uint2 H8 = *reinterpret_cast<const uint2*>(&ahs[ro + 8 * S3]);
                uint2 L0 = *reinterpret_cast<const uint2*>(&als[ro]);
                uint2 L8 = *reinterpret_cast<const uint2*>(&als[ro + 8 * S3]);
                uint32_t ah_[4] = { H0.x, H8.x, H0.y, H8.y };
                uint32_t al_[4] = { L0.x, L8.x, L0.y, L8.y };
                #pragma unroll
                for (int ni = 0; ni < 4; ni++) {
                    mma_tf32(acc[mi][ni], ah_, bl[ni]);
                    mma_tf32(acc[mi][ni], al_, bh[ni]);
                    mma_tf32(acc[mi][ni], ah_, bh[ni]);
                }
            }
        }
        __syncthreads();
    }
    #undef S3_ISSUE

    if (EPI == 2) {
        float* stg = reinterpret_cast<float*>(sm);
        #pragma unroll
        for (int mi = 0; mi < 4; mi++) {
            const int r = wm * 64 + mi * 16 + l4;
            #pragma unroll
            for (int ni = 0; ni < 4; ni++) {
                const int c = wn * 32 + ni * 8 + 2 * lm;
                stg[r * SS + c]           = acc[mi][ni][0];
                stg[r * SS + c + 1]       = acc[mi][ni][1];
                stg[(r + 8) * SS + c]     = acc[mi][ni][2];
                stg[(r + 8) * SS + c + 1] = acc[mi][ni][3];
            }
        }
        __syncthreads();
        float* Cbh = Chs + (size_t)bt * strideC;
        float* Cbl = Cls + (size_t)bt * strideC;
        for (int e = t; e < 128 * 128; e += 256) {
            const int r = e >> 7, p = e & 127;
            const int j = (p & ~7) | invp(p & 7);
            float v = stg[r * SS + j] + biassel[j];
            float h = tf32f(v);
            const size_t off = (size_t)(m0 + r) * ldc + p;
            Cbh[off] = h;
            Cbl[off] = tf32f(v - h);
        }
    } else {
        float* Cb = Ch + (size_t)bt * strideC;
        #pragma unroll
        for (int mi = 0; mi < 4; mi++) {
            const int gr = m0 + wm * 64 + mi * 16 + l4;
            #pragma unroll
            for (int ni = 0; ni < 4; ni++) {
                const int gc = n0 + wn * 32 + ni * 8 + lm * 2;
                float2 o0 = { acc[mi][ni][0], acc[mi][ni][1] };
                float2 o1 = { acc[mi][ni][2], acc[mi][ni][3] };
                *reinterpret_cast<float2*>(&Cb[(size_t)gr * ldc + gc]) = o0;
                *reinterpret_cast<float2*>(&Cb[(size_t)(gr + 8) * ldc + gc]) = o1;
            }
        }
    }
}

// ---------------------------------------------------------------------------
// Launch
// ---------------------------------------------------------------------------
extern "C" void kernel_launch(void* const* d_in, const int* in_sizes, int n_in,
                              void* d_out, int out_size) {
    const float* img   = (const float*)d_in[0];
    const float* tac   = (const float*)d_in[1];
    const float* Wq    = (const float*)d_in[2];
    const float* bq    = (const float*)d_in[3];
    const float* Wk    = (const float*)d_in[4];
    const float* bk    = (const float*)d_in[5];
    const float* Wv    = (const float*)d_in[6];
    const float* bv    = (const float*)d_in[7];
    const float* gamma = (const float*)d_in[8];
    float* out = (float*)d_out;

    float *gX, *gXTh, *gXTl, *gWqh, *gWql, *gWkh, *gWkl, *gWvh;
    float *gQTh, *gQTl, *gKTh, *gKTl, *gVh, *gA;
    cudaGetSymbolAddress((void**)&gX,   g_X);
    cudaGetSymbolAddress((void**)&gXTh, g_XTh);
    cudaGetSymbolAddress((void**)&gXTl, g_XTl);
    cudaGetSymbolAddress((void**)&gWqh, g_Wqh);
    cudaGetSymbolAddress((void**)&gWql, g_Wql);
    cudaGetSymbolAddress((void**)&gWkh, g_Wkh);
    cudaGetSymbolAddress((void**)&gWkl, g_Wkl);
    cudaGetSymbolAddress((void**)&gWvh, g_Wvh);
    cudaGetSymbolAddress((void**)&gQTh, g_QTh);
    cudaGetSymbolAddress((void**)&gQTl, g_QTl);
    cudaGetSymbolAddress((void**)&gKTh, g_KTh);
    cudaGetSymbolAddress((void**)&gKTl, g_KTl);
    cudaGetSymbolAddress((void**)&gVh,  g_Vh);
    cudaGetSymbolAddress((void**)&gA,   g_ATT);

    cudaFuncSetAttribute(gemm_s1_kernel<0>, cudaFuncAttributeMaxDynamicSharedMemorySize, SMEM_S1);
    cudaFuncSetAttribute(gemm_s1_kernel<1>, cudaFuncAttributeMaxDynamicSharedMemorySize, SMEM_S1);
    cudaFuncSetAttribute(gemm_s3_kernel<2>, cudaFuncAttributeMaxDynamicSharedMemorySize, SMEM_S3);
    cudaFuncSetAttribute(gemm_s3_kernel<3>, cudaFuncAttributeMaxDynamicSharedMemorySize, SMEM_S3);

    // 1) residual + prepared XT + prepared weights
    build_x_kernel <<<dim3((NP + 255) / 256, CF, BT), 256>>>(img, tac);
    build_xt_kernel<<<dim3(CF / 256, NP, BT), 256>>>(img, tac);
    prep_split_kernel<<<(CQ * CF + 255) / 256, 256>>>(Wq, gWqh, gWql, CQ * CF);
    prep_split_kernel<<<(CQ * CF + 255) / 256, 256>>>(Wk, gWkh, gWkl, CQ * CF);
    prep_round_kernel<<<(CF * CF + 255) / 256, 256>>>(Wv, gWvh, CF * CF);

    // 2) fused q+k projections (3xTF32): QT/KT[n][o] split+permuted
    gemm_s3_kernel<2><<<dim3(NP / 128, 2, BT), 256, SMEM_S3>>>(
        gXTh, gXTl, CF, (size_t)NP * CF,
        gWqh, gWql, gWkh, gWkl, CF, 0,
        CF, bq, bk,
        gQTh, gQTl, gKTh, gKTl, CQ, (size_t)NP * CQ);

    // 3) v projection: V_hi[c][n] (rounded, n-permuted)
    gemm_s1_kernel<0><<<dim3(CF / 128, NP / 128, BT), 256, SMEM_S1>>>(
        gWvh, CF, 0,
        gXTh, CF, (size_t)NP * CF,
        CF, bv, nullptr, nullptr,
        gVh, NP, (size_t)CF * NP);

    // 4) attention scores (3xTF32): raw S[n][m]
    gemm_s3_kernel<3><<<dim3(NP / 128, NP / 128, BT), 256, SMEM_S3>>>(
        gQTh, gQTl, CQ, (size_t)NP * CQ,
        gKTh, gKTl, nullptr, nullptr, CQ, (size_t)NP * CQ,
        CQ, nullptr, nullptr,
        gA, nullptr, nullptr, nullptr, NP, (size_t)NP * NP);

    // 5) softmax -> probs rounded + permuted
    softmax_kernel<<<dim3(NTOK, BT), 256>>>();

    // 6) out = gamma * (V @ P^T) + X
    gemm_s1_kernel<1><<<dim3(CF / 128, NP / 128, BT), 256, SMEM_S1>>>(
        gVh, NP, (size_t)CF * NP,
        gA, NP, (size_t)NP * NP,
        NP, nullptr, gamma, gX,
        out, NTOK, (size_t)CF * NTOK);
}

// round 12
// speedup vs baseline: 1.2842x; 1.2842x over previous
#include <cuda_runtime.h>
#include <cstdint>

// ---------------------------------------------------------------------------
// Shapes
// ---------------------------------------------------------------------------
#define BT   12
#define CF   1024
#define CQ   128
#define NTOK 2401
#define NP   2432
#define HF   49

// ---------------------------------------------------------------------------
// Scratch
// ---------------------------------------------------------------------------
__device__ float g_X  [(size_t)BT * CF * NP];   // residual [bt][c][n]
__device__ float g_XT [(size_t)BT * NP * CF];   // raw XT (q/k path)
__device__ float g_XTh[(size_t)BT * NP * CF];   // tf32-rounded XT (v path)
__device__ float g_Wvh[(size_t)CF * CF];        // tf32-rounded Wv
__device__ float g_QT [(size_t)BT * NP * CQ];   // raw q
__device__ float g_KT [(size_t)BT * NP * CQ];   // raw k
__device__ float g_V  [(size_t)BT * CF * NP];   // tf32-rounded v (incl bias)
__device__ float g_ATT[(size_t)BT * NP * NP];   // raw scores -> tf32-rounded probs

__device__ __forceinline__ uint32_t f2tf(float f) {
    uint32_t u; asm("cvt.rna.tf32.f32 %0, %1;" : "=r"(u) : "f"(f)); return u;
}
__device__ __forceinline__ float tf32f(float f) { return __uint_as_float(f2tf(f)); }
__device__ __forceinline__ uint32_t u2tf(uint32_t x) {
    uint32_t u; asm("cvt.rna.tf32.f32 %0, %1;" : "=r"(u) : "f"(__uint_as_float(x))); return u;
}
__device__ __forceinline__ uint32_t smem_u32(const void* p) {
    uint32_t a;
    asm("{ .reg .u64 t; cvta.to.shared.u64 t, %1; cvt.u32.u64 %0, t; }" : "=r"(a) : "l"(p));
    return a;
}

__device__ __forceinline__ void mma_tf32(float c[4], const uint32_t a[4], const uint32_t b[2]) {
    asm volatile(
        "mma.sync.aligned.m16n8k8.row.col.f32.tf32.tf32.f32 "
        "{%0,%1,%2,%3}, {%4,%5,%6,%7}, {%8,%9}, {%0,%1,%2,%3};"
        : "+f"(c[0]), "+f"(c[1]), "+f"(c[2]), "+f"(c[3])
        : "r"(a[0]), "r"(a[1]), "r"(a[2]), "r"(a[3]), "r"(b[0]), "r"(b[1]));
}

#define CP_ASYNC16(dst_u32, src_ptr) \
    asm volatile("cp.async.cg.shared.global [%0], [%1], 16;" :: "r"(dst_u32), "l"(src_ptr) : "memory")
#define CP_COMMIT() asm volatile("cp.async.commit_group;" ::: "memory")
#define CP_WAIT0()  asm volatile("cp.async.wait_group 0;" ::: "memory")
#define CP_WAIT1()  asm volatile("cp.async.wait_group 1;" ::: "memory")

// ---------------------------------------------------------------------------
// 1a) residual X[bt][c][n]
// ---------------------------------------------------------------------------
__global__ void build_x_kernel(const float* __restrict__ img,
                               const float* __restrict__ tac) {
    int n = blockIdx.x * 256 + threadIdx.x;
    int c = blockIdx.y, bt = blockIdx.z;
    if (n >= NP) return;
    float v = 0.0f;
    if (n < NTOK) {
        int i = n / HF, j = n % HF;
        v = (c < 512)
            ? tac[(((size_t)bt * 512 + c) * 7 + (i / 7)) * 7 + (j / 7)]
            : img[(((size_t)bt * 512 + (c - 512)) * 7 + (i % 7)) * 7 + (j % 7)];
    }
    g_X[((size_t)bt * CF + c) * NP + n] = v;
}

// ---------------------------------------------------------------------------
// 1b) XT raw + rounded (zero rows for n >= NTOK)
// ---------------------------------------------------------------------------
__global__ void build_xt_kernel(const float* __restrict__ img,
                                const float* __restrict__ tac) {
    int c = blockIdx.x * 256 + threadIdx.x;
    int n = blockIdx.y, bt = blockIdx.z;
    if (c >= CF) return;
    float v = 0.0f;
    if (n < NTOK) {
        int i = n / HF, j = n % HF;
        v = (c < 512)
            ? tac[(((size_t)bt * 512 + c) * 7 + (i / 7)) * 7 + (j / 7)]
            : img[(((size_t)bt * 512 + (c - 512)) * 7 + (i % 7)) * 7 + (j % 7)];
    }
    size_t base = ((size_t)bt * NP + n) * CF + c;
    g_XT[base]  = v;
    g_XTh[base] = tf32f(v);
}

// ---------------------------------------------------------------------------
// 1c) Wv -> rounded
// ---------------------------------------------------------------------------
__global__ void prep_round_kernel(const float* __restrict__ src,
                                  float* __restrict__ dst, int n) {
    int i = blockIdx.x * 256 + threadIdx.x;
    if (i < n) dst[i] = tf32f(src[i]);
}

// ---------------------------------------------------------------------------
// 2) row softmax (m < 2401), writes tf32-rounded probs, zeroes padding
// ---------------------------------------------------------------------------
__global__ __launch_bounds__(256)
void softmax_kernel() {
    __shared__ float row[NTOK];
    __shared__ float red[256];
    const int n = blockIdx.x, bt = blockIdx.y;
    float* base = g_ATT + ((size_t)bt * NP + n) * NP;
    const int t = threadIdx.x;

    float mx = -1e30f;
    for (int m = t; m < NTOK; m += 256) { float v = base[m]; row[m] = v; mx = fmaxf(mx, v); }
    red[t] = mx; __syncthreads();
    for (int s = 128; s > 0; s >>= 1) { if (t < s) red[t] = fmaxf(red[t], red[t + s]); __syncthreads(); }
    mx = red[0]; __syncthreads();

    float sum = 0.0f;
    for (int m = t; m < NTOK; m += 256) { float e = __expf(row[m] - mx); row[m] = e; sum += e; }
    red[t] = sum; __syncthreads();
    for (int s = 128; s > 0; s >>= 1) { if (t < s) red[t] += red[t + s]; __syncthreads(); }
    float inv = 1.0f / red[0];

    for (int m = t; m < NTOK; m += 256) base[m] = tf32f(row[m] * inv);
    for (int m = NTOK + t; m < NP; m += 256) base[m] = 0.0f;
}

// ---------------------------------------------------------------------------
// Shared tiling constants (stride-36 layout, conflict-free scalar LDS)
// ---------------------------------------------------------------------------
#define LDS_S 36
#define TILEW (128 * LDS_S)            // words per 128x32 tile
#define SMEM_T (4 * TILEW * 4)         // 73728 B double buffer

// ---------------------------------------------------------------------------
// 3) SPLIT=1 GEMM on PRE-ROUNDED operands: pure LDS+MMA mainloop (no cvt).
//    C[M,N] = A[M,K] @ B[N,K]^T (both K-major). 256 thr (8 warps 2Mx4N,
//    warp tile 64x32), chunk 32, 2-stage cp.async, 2 CTAs/SM.
//    EPI 0: C = tf32f(acc + bias[row])   (v writeback, pre-rounded for PV)
//    EPI 1: C = gamma*acc + X[row][col], col<NTOK  (final output, fp32)
// ---------------------------------------------------------------------------
template <int EPI>
__global__ __launch_bounds__(256, 2)
void gemm_async_kernel(const float* __restrict__ A, int lda, size_t strideA,
                       const float* __restrict__ B, int ldb, size_t strideB,
                       int K,
                       const float* __restrict__ bias,
                       const float* __restrict__ gamma,
                       const float* __restrict__ Xres,
                       float* __restrict__ C, int ldc, size_t strideC) {
    extern __shared__ uint32_t sm[];
    const uint32_t smem_base = smem_u32(sm);

    const int bt = blockIdx.z;
    const int m0 = blockIdx.x * 128;
    const int n0 = blockIdx.y * 128;
    const float* Ab = A + (size_t)bt * strideA + (size_t)m0 * lda;
    const float* Bb = B + (size_t)bt * strideB + (size_t)n0 * ldb;

    const int t = threadIdx.x;
    const int wid = t >> 5, lane = t & 31;
    const int warp_m = wid & 1, warp_n = wid >> 1;
    const int l4 = lane >> 2, lm = lane & 3;

    const int prow = t >> 1;
    const int pcol = (t & 1) * 16;
    const float* aRow = Ab + (size_t)prow * lda + pcol;
    const float* bRow = Bb + (size_t)prow * ldb + pcol;
    const uint32_t sA0 = smem_base + (prow * LDS_S + pcol) * 4;
    const uint32_t sB0 = sA0 + TILEW * 4;

    float acc[4][4][4];
    #pragma unroll
    for (int mi = 0; mi < 4; mi++)
        #pragma unroll
        for (int ni = 0; ni < 4; ni++)
            #pragma unroll
            for (int r = 0; r < 4; r++) acc[mi][ni][r] = 0.0f;

    const int NCH = K / 32;

    #pragma unroll
    for (int q = 0; q < 4; q++) {
        CP_ASYNC16(sA0 + q * 16, aRow + q * 4);
        CP_ASYNC16(sB0 + q * 16, bRow + q * 4);
    }
    CP_COMMIT();

    for (int ch = 0; ch < NCH; ch++) {
        const int buf = ch & 1;
        if (ch + 1 < NCH) {
            const int k1 = (ch + 1) * 32;
            const uint32_t dA = sA0 + (buf ^ 1) * (2 * TILEW * 4);
            const uint32_t dB = sB0 + (buf ^ 1) * (2 * TILEW * 4);
            #pragma unroll
            for (int q = 0; q < 4; q++) {
                CP_ASYNC16(dA + q * 16, aRow + k1 + q * 4);
                CP_ASYNC16(dB + q * 16, bRow + k1 + q * 4);
            }
            CP_COMMIT();
            CP_WAIT1();
        } else {
            CP_WAIT0();
        }
        __syncthreads();

        const uint32_t* as = sm + buf * 2 * TILEW;
        const uint32_t* bs = as + TILEW;
        #pragma unroll
        for (int g = 0; g < 4; g++) {
            const int kk = g * 8;
            uint32_t b[4][2];
            #pragma unroll
            for (int ni = 0; ni < 4; ni++) {
                const int base = (warp_n * 32 + ni * 8 + l4) * LDS_S + kk + lm;
                b[ni][0] = bs[base];
                b[ni][1] = bs[base + 4];
            }
            #pragma unroll
            for (int mi = 0; mi < 4; mi++) {
                const int base = (warp_m * 64 + mi * 16 + l4) * LDS_S + kk + lm;
                uint32_t a[4];
                a[0] = as[base];
                a[1] = as[base + 8 * LDS_S];
                a[2] = as[base + 4];
                a[3] = as[base + 8 * LDS_S + 4];
                #pragma unroll
                for (int ni = 0; ni < 4; ni++) mma_tf32(acc[mi][ni], a, b[ni]);
            }
        }
        __syncthreads();
    }

    float* Cb = C + (size_t)bt * strideC;
    if (EPI == 0) {
        #pragma unroll
        for (int mi = 0; mi < 4; mi++) {
            const int gr = m0 + warp_m * 64 + mi * 16 + l4;
            const float bv0 = bias[gr], bv8 = bias[gr + 8];
            #pragma unroll
            for (int ni = 0; ni < 4; ni++) {
                const int gc = n0 + warp_n * 32 + ni * 8 + lm * 2;
                float2 o0 = { tf32f(acc[mi][ni][0] + bv0), tf32f(acc[mi][ni][1] + bv0) };
                float2 o1 = { tf32f(acc[mi][ni][2] + bv8), tf32f(acc[mi][ni][3] + bv8) };
                *reinterpret_cast<float2*>(&Cb[(size_t)gr * ldc + gc]) = o0;
                *reinterpret_cast<float2*>(&Cb[(size_t)(gr + 8) * ldc + gc]) = o1;
            }
        }
    } else {
        const float g = __ldg(gamma);
        const float* Xb = Xres + (size_t)bt * CF * NP;
        #pragma unroll
        for (int mi = 0; mi < 4; mi++) {
            const int gr = m0 + warp_m * 64 + mi * 16 + l4;
            #pragma unroll
            for (int ni = 0; ni < 4; ni++) {
                const int gc = n0 + warp_n * 32 + ni * 8 + lm * 2;
                if (gc < NTOK)
                    Cb[(size_t)gr * ldc + gc] = g * acc[mi][ni][0] + Xb[(size_t)gr * NP + gc];
                if (gc + 1 < NTOK)
                    Cb[(size_t)gr * ldc + gc + 1] = g * acc[mi][ni][1] + Xb[(size_t)gr * NP + gc + 1];
                if (gc < NTOK)
                    Cb[(size_t)(gr + 8) * ldc + gc] = g * acc[mi][ni][2] + Xb[(size_t)(gr + 8) * NP + gc];
                if (gc + 1 < NTOK)
                    Cb[(size_t)(gr + 8) * ldc + gc + 1] = g * acc[mi][ni][3] + Xb[(size_t)(gr + 8) * NP + gc + 1];
            }
        }
    }
}

// ---------------------------------------------------------------------------
// 4) SPLIT=3 (3xTF32) GEMM — R8 form, unchanged: cp.async double-buffered raw
//    staging, hi/lo split on consume, 256 threads, 2 CTAs/SM.
//    EPI 2: fused q/k projection (blockIdx.y selects B/bias/C), C = acc + bias[col]
//    EPI 3: C = acc (raw scores)
// ---------------------------------------------------------------------------
template <int EPI>
__global__ __launch_bounds__(256, 2)
void gemm_async3_kernel(const float* __restrict__ A, int lda, size_t strideA,
                        const float* __restrict__ B, int ldb, size_t strideB,
                        const float* __restrict__ B2,
                        int K,
                        const float* __restrict__ bias,
                        const float* __restrict__ bias2,
                        float* __restrict__ C, int ldc, size_t strideC,
                        float* __restrict__ C2) {
    extern __shared__ uint32_t sm[];
    const uint32_t smem_base = smem_u32(sm);

    const int bt = blockIdx.z;
    const int m0 = blockIdx.x * 128;
    int n0;
    const float* Bsel;
    const float* biassel;
    float* Csel;
    if (EPI == 2) {
        n0 = 0;
        const bool alt = (blockIdx.y != 0);
        Bsel = alt ? B2 : B;
        biassel = alt ? bias2 : bias;
        Csel = alt ? C2 : C;
    } else {
        n0 = blockIdx.y * 128;
        Bsel = B; biassel = bias; Csel = C;
    }

    const float* Ab = A + (size_t)bt * strideA + (size_t)m0 * lda;
    const float* Bb = Bsel + (size_t)bt * strideB + (size_t)n0 * ldb;

    const int t = threadIdx.x;
    const int wid = t >> 5, lane = t & 31;
    const int warp_m = wid & 1, warp_n = wid >> 1;
    const int l4 = lane >> 2, lm = lane & 3;

    const int prow = t >> 1;
    const int pcol = (t & 1) * 16;
    const float* aRow = Ab + (size_t)prow * lda + pcol;
    const float* bRow = Bb + (size_t)prow * ldb + pcol;
    const uint32_t sA0 = smem_base + (prow * LDS_S + pcol) * 4;
    const uint32_t sB0 = sA0 + TILEW * 4;

    float acc[4][4][4];
    #pragma unroll
    for (int mi = 0; mi < 4; mi++)
        #pragma unroll
        for (int ni = 0; ni < 4; ni++)
            #pragma unroll
            for (int r = 0; r < 4; r++) acc[mi][ni][r] = 0.0f;

    const int NCH = K / 32;

    #pragma unroll
    for (int q = 0; q < 4; q++) {
        CP_ASYNC16(sA0 + q * 16, aRow + q * 4);
        CP_ASYNC16(sB0 + q * 16, bRow + q * 4);
    }
    CP_COMMIT();

    for (int ch = 0; ch < NCH; ch++) {
        const int buf = ch & 1;
        if (ch + 1 < NCH) {
            const int k1 = (ch + 1) * 32;
            const uint32_t dA = sA0 + (buf ^ 1) * (2 * TILEW * 4);
            const uint32_t dB = sB0 + (buf ^ 1) * (2 * TILEW * 4);
            #pragma unroll
            for (int q = 0; q < 4; q++) {
                CP_ASYNC16(dA + q * 16, aRow + k1 + q * 4);
                CP_ASYNC16(dB + q * 16, bRow + k1 + q * 4);
            }
            CP_COMMIT();
            CP_WAIT1();
        } else {
            CP_WAIT0();
        }
        __syncthreads();

        const uint32_t* as = sm + buf * 2 * TILEW;
        const uint32_t* bs = as + TILEW;
        #pragma unroll
        for (int g = 0; g < 4; g++) {
            const int kk = g * 8;
            uint32_t bh[4][2], bl[4][2];
            #pragma unroll
            for (int ni = 0; ni < 4; ni++) {
                const int base = (warp_n * 32 + ni * 8 + l4) * LDS_S + kk + lm;
                const uint32_t r0 = bs[base], r1 = bs[base + 4];
                bh[ni][0] = u2tf(r0);
                bl[ni][0] = f2tf(__uint_as_float(r0) - __uint_as_float(bh[ni][0]));
                bh[ni][1] = u2tf(r1);
                bl[ni][1] = f2tf(__uint_as_float(r1) - __uint_as_float(bh[ni][1]));
            }
            #pragma unroll
            for (int mi = 0; mi < 4; mi++) {
                const int base = (warp_m * 64 + mi * 16 + l4) * LDS_S + kk + lm;
                uint32_t ar[4];
                ar[0] = as[base];
                ar[1] = as[base + 8 * LDS_S];
                ar[2] = as[base + 4];
                ar[3] = as[base + 8 * LDS_S + 4];
                uint32_t ah[4], al[4];
                #pragma unroll
                for (int r = 0; r < 4; r++) {
                    ah[r] = u2tf(ar[r]);
                    al[r] = f2tf(__uint_as_float(ar[r]) - __uint_as_float(ah[r]));
                }
                #pragma unroll
                for (int ni = 0; ni < 4; ni++) {
                    mma_tf32(acc[mi][ni], ah, bl[ni]);
                    mma_tf32(acc[mi][ni], al, bh[ni]);
                    mma_tf32(acc[mi][ni], ah, bh[ni]);
                }
            }
        }
        __syncthreads();
    }

    float* Cb = Csel + (size_t)bt * strideC;
    if (EPI == 2) {
        #pragma unroll
        for (int mi = 0; mi < 4; mi++) {
            const int gr = m0 + warp_m * 64 + mi * 16 + l4;
            #pragma unroll
            for (int ni = 0; ni < 4; ni++) {
                const int gc = n0 + warp_n * 32 + ni * 8 + lm * 2;
                const float b0 = biassel[gc], b1 = biassel[gc + 1];
                float2 o0 = { acc[mi][ni][0] + b0, acc[mi][ni][1] + b1 };
                float2 o1 = { acc[mi][ni][2] + b0, acc[mi][ni][3] + b1 };
                *reinterpret_cast<float2*>(&Cb[(size_t)gr * ldc + gc]) = o0;
                *reinterpret_cast<float2*>(&Cb[(size_t)(gr + 8) * ldc + gc]) = o1;
            }
        }
    } else {
        #pragma unroll
        for (int mi = 0; mi < 4; mi++) {
            const int gr = m0 + warp_m * 64 + mi * 16 + l4;
            #pragma unroll
            for (int ni = 0; ni < 4; ni++) {
                const int gc = n0 + warp_n * 32 + ni * 8 + lm * 2;
                float2 o0 = { acc[mi][ni][0], acc[mi][ni][1] };
                float2 o1 = { acc[mi][ni][2], acc[mi][ni][3] };
                *reinterpret_cast<float2*>(&Cb[(size_t)gr * ldc + gc]) = o0;
                *reinterpret_cast<float2*>(&Cb[(size_t)(gr + 8) * ldc + gc]) = o1;
            }
        }
    }
}

// ---------------------------------------------------------------------------
// Launch
// ---------------------------------------------------------------------------
extern "C" void kernel_launch(void* const* d_in, const int* in_sizes, int n_in,
                              void* d_out, int out_size) {
    const float* img   = (const float*)d_in[0];
    const float* tac   = (const float*)d_in[1];
    const float* Wq    = (const float*)d_in[2];
    const float* bq    = (const float*)d_in[3];
    const float* Wk    = (const float*)d_in[4];
    const float* bk    = (const float*)d_in[5];
    const float* Wv    = (const float*)d_in[6];
    const float* bv    = (const float*)d_in[7];
    const float* gamma = (const float*)d_in[8];
    float* out = (float*)d_out;

    float *gX, *gXT, *gXTh, *gWvh, *gQT, *gKT, *gV, *gA;
    cudaGetSymbolAddress((void**)&gX,   g_X);
    cudaGetSymbolAddress((void**)&gXT,  g_XT);
    cudaGetSymbolAddress((void**)&gXTh, g_XTh);
    cudaGetSymbolAddress((void**)&gWvh, g_Wvh);
    cudaGetSymbolAddress((void**)&gQT,  g_QT);
    cudaGetSymbolAddress((void**)&gKT,  g_KT);
    cudaGetSymbolAddress((void**)&gV,   g_V);
    cudaGetSymbolAddress((void**)&gA,   g_ATT);

    cudaFuncSetAttribute(gemm_async_kernel<0>,  cudaFuncAttributeMaxDynamicSharedMemorySize, SMEM_T);
    cudaFuncSetAttribute(gemm_async_kernel<1>,  cudaFuncAttributeMaxDynamicSharedMemorySize, SMEM_T);
    cudaFuncSetAttribute(gemm_async3_kernel<2>, cudaFuncAttributeMaxDynamicSharedMemorySize, SMEM_T);
    cudaFuncSetAttribute(gemm_async3_kernel<3>, cudaFuncAttributeMaxDynamicSharedMemorySize, SMEM_T);

    // 1) residual + XT (raw + rounded) + rounded Wv
    build_x_kernel <<<dim3((NP + 255) / 256, CF, BT), 256>>>(img, tac);
    build_xt_kernel<<<dim3(CF / 256, NP, BT), 256>>>(img, tac);
    prep_round_kernel<<<(CF * CF + 255) / 256, 256>>>(Wv, gWvh, CF * CF);

    // 2) fused q+k projections (3xTF32, raw operands, split on consume)
    gemm_async3_kernel<2><<<dim3(NP / 128, 2, BT), 256, SMEM_T>>>(
        gXT, CF, (size_t)NP * CF,
        Wq, CF, 0, Wk,
        CF, bq, bk,
        gQT, CQ, (size_t)NP * CQ, gKT);

    // 3) v projection (pre-rounded operands, no cvt in mainloop)
    gemm_async_kernel<0><<<dim3(CF / 128, NP / 128, BT), 256, SMEM_T>>>(
        gWvh, CF, 0,
        gXTh, CF, (size_t)NP * CF,
        CF, bv, nullptr, nullptr,
        gV, NP, (size_t)CF * NP);

    // 4) attention scores (3xTF32, raw q/k, split on consume)
    gemm_async3_kernel<3><<<dim3(NP / 128, NP / 128, BT), 256, SMEM_T>>>(
        gQT, CQ, (size_t)NP * CQ,
        gKT, CQ, (size_t)NP * CQ, nullptr,
        CQ, nullptr, nullptr,
        gA, NP, (size_t)NP * NP, nullptr);

    // 5) softmax -> tf32-rounded probs
    softmax_kernel<<<dim3(NTOK, BT), 256>>>();

    // 6) out = gamma * (V @ P^T) + X (pre-rounded V and P, no cvt)
    gemm_async_kernel<1><<<dim3(CF / 128, NP / 128, BT), 256, SMEM_T>>>(
        gV, NP, (size_t)CF * NP,
        gA, NP, (size_t)NP * NP,
        NP, nullptr, gamma, gX,
        out, NTOK, (size_t)CF * NTOK);
}